// round 1
// baseline (speedup 1.0000x reference)
#include <cuda_runtime.h>
#include <cuda_bf16.h>
#include <cstdint>

// LaplacianLoss: out[b] = ||w * (L @ x[b])||_F * NV
//   L: [NV, NV] f32 (400 MB, streamed once)
//   x: [8, NV, 3] f32  -> repacked to X[c][j], c = 3*b + k (24 channels)
//   out: 8 f32
//
// Fused GEMM [NV,NV]@[NV,24] with register-tiled f32x2 FMAs, smem-staged X,
// j split in 2 halves for wave balance, partial lx -> static buffer,
// epilogue kernel does sum-of-squares + sqrt. No allocations, no atomics.

#define NVTX     10000
#define NCH      24            // 8 batches * 3 dims
#define JHALF    5000          // j range per grid.y slice
#define JT       256           // j tile staged in smem
#define RPW      6             // rows per warp (accumulator tile)
#define WARPS    8
#define ROWS_CTA (WARPS * RPW) // 48
#define NRB      ((NVTX + ROWS_CTA - 1) / ROWS_CTA) // 209 row blocks

typedef unsigned long long ull;

// X repacked as [6][NV] float4: quad q holds channels 4q..4q+3 for vertex j.
__device__ float4 g_X4[6 * NVTX];
// Partial lx: [jhalf][row][12] f32x2 pairs (pair p = channels 2p, 2p+1).
__device__ ull g_part[2 * NVTX * 12];

#define FFMA2(d, a, b) asm("fma.rn.f32x2 %0, %1, %2, %0;" : "+l"(d) : "l"(a), "l"(b))
#define FADD2(d, a, b) asm("add.rn.f32x2 %0, %1, %2;" : "=l"(d) : "l"(a), "l"(b))
#define PACK2(d, f)    asm("mov.b64 %0, {%1, %1};"     : "=l"(d) : "f"(f))

// ---------------------------------------------------------------------------
// Kernel 0: repack x[8][NV][3] -> g_X4[c/4][j].{c%4}
// ---------------------------------------------------------------------------
__global__ void k_buildx(const float* __restrict__ x) {
    int idx = blockIdx.x * blockDim.x + threadIdx.x;   // over NV*24
    if (idx >= NVTX * NCH) return;
    int j = idx / NCH;
    int c = idx - j * NCH;
    int b = c / 3;
    int k = c - 3 * b;
    float v = x[(b * NVTX + j) * 3 + k];
    reinterpret_cast<float*>(g_X4)[(c >> 2) * (NVTX * 4) + j * 4 + (c & 3)] = v;
}

// ---------------------------------------------------------------------------
// Kernel 1: main GEMM. grid = (NRB, 2), block = 256.
//   blockIdx.x -> row block (48 rows), blockIdx.y -> j half.
// ---------------------------------------------------------------------------
__global__ void __launch_bounds__(256) k_main(const float* __restrict__ L) {
    __shared__ float4 Xs[6][JT];

    const int tid  = threadIdx.x;
    const int lane = tid & 31;
    const int warp = tid >> 5;
    const int jh   = blockIdx.y;
    const int row0 = blockIdx.x * ROWS_CTA + warp * RPW;
    const int jbeg = jh * JHALF;
    const int jend = jbeg + JHALF;

    // accumulators: 6 rows x 12 channel-pairs (f32x2)
    ull acc[RPW][12];
#pragma unroll
    for (int r = 0; r < RPW; r++)
#pragma unroll
        for (int p = 0; p < 12; p++) acc[r][p] = 0ULL;

    // per-row L base pointers (row-clamped; OOB rows guarded at store time)
    const float* Lp[RPW];
#pragma unroll
    for (int r = 0; r < RPW; r++) {
        int rr = row0 + r;
        if (rr >= NVTX) rr = NVTX - 1;
        Lp[r] = L + (size_t)rr * NVTX + jbeg + lane;
    }

    // depth-2 software prefetch of L (steps of 32 j)
    float Lpre[2][RPW];
#pragma unroll
    for (int q = 0; q < 2; q++) {
#pragma unroll
        for (int r = 0; r < RPW; r++)
            Lpre[q][r] = __ldcs(Lp[r] + q * 32);   // first 64 j always in-range
    }

    const int ntiles = (JHALF + JT - 1) / JT;      // 20
    int gs = 0;                                    // global 32-j step index

    for (int t = 0; t < ntiles; t++) {
        // stage X tile (zero-padded past jend)
        {
            int jg = jbeg + t * JT + tid;
            float4 z = make_float4(0.f, 0.f, 0.f, 0.f);
            bool ok = (jg < jend);
#pragma unroll
            for (int p4 = 0; p4 < 6; p4++)
                Xs[p4][tid] = ok ? __ldg(&g_X4[p4 * NVTX + jg]) : z;
        }
        __syncthreads();

#pragma unroll
        for (int s = 0; s < JT / 32; s++) {
            const int buf = gs & 1;

            // pack current L values (duplicate into both f32x2 halves)
            ull a[RPW];
#pragma unroll
            for (int r = 0; r < RPW; r++) PACK2(a[r], Lpre[buf][r]);

            // prefetch step gs+2 (clamped offset, zero-selected if OOB)
            {
                int jq  = gs + 2;
                int jj  = jbeg + jq * 32 + lane;
                bool ok = (jj < jend);
                int off = ok ? jq * 32 : 0;
#pragma unroll
                for (int r = 0; r < RPW; r++) {
                    float v = __ldcs(Lp[r] + off);
                    Lpre[buf][r] = ok ? v : 0.f;
                }
            }

            // 72 packed FMAs: 6 channel-quads x 6 rows x 2 pairs
            const int xi = s * 32 + lane;
#pragma unroll
            for (int p4 = 0; p4 < 6; p4++) {
                ulonglong2 xv = *reinterpret_cast<const ulonglong2*>(&Xs[p4][xi]);
#pragma unroll
                for (int r = 0; r < RPW; r++) {
                    FFMA2(acc[r][2 * p4 + 0], a[r], xv.x);
                    FFMA2(acc[r][2 * p4 + 1], a[r], xv.y);
                }
            }
            gs++;
        }
        __syncthreads();
    }

    // lane-reduce each (row, pair) across the warp (butterfly, f32x2 adds)
#pragma unroll
    for (int r = 0; r < RPW; r++) {
#pragma unroll
        for (int p = 0; p < 12; p++) {
            ull v = acc[r][p];
#pragma unroll
            for (int m = 16; m >= 1; m >>= 1) {
                ull o = __shfl_xor_sync(0xffffffffu, v, m);
                ull s;
                FADD2(s, v, o);
                v = s;
            }
            acc[r][p] = v;
        }
    }

    if (lane == 0) {
#pragma unroll
        for (int r = 0; r < RPW; r++) {
            int row = row0 + r;
            if (row < NVTX) {
#pragma unroll
                for (int p = 0; p < 12; p++)
                    g_part[((size_t)jh * NVTX + row) * 12 + p] = acc[r][p];
            }
        }
    }
}

// ---------------------------------------------------------------------------
// Kernel 2: finalize. One block per batch. out[b] = w * NV * sqrt(sum lx^2).
// ---------------------------------------------------------------------------
__global__ void k_final(const float* __restrict__ w, float* __restrict__ out) {
    const int b = blockIdx.x;
    const int tid = threadIdx.x;
    __shared__ float red[256];

    const float* P = reinterpret_cast<const float*>(g_part); // [jh][row][24]
    float s = 0.f;
    for (int idx = tid; idx < NVTX * 3; idx += 256) {
        int i = idx / 3;
        int k = idx - 3 * i;
        int c = 3 * b + k;
        float v = P[(size_t)i * 24 + c] + P[((size_t)NVTX + i) * 24 + c];
        s += v * v;
    }
    red[tid] = s;
    __syncthreads();
    for (int off = 128; off > 0; off >>= 1) {
        if (tid < off) red[tid] += red[tid + off];
        __syncthreads();
    }
    if (tid == 0) out[b] = w[0] * (float)NVTX * sqrtf(red[0]);
}

// ---------------------------------------------------------------------------
extern "C" void kernel_launch(void* const* d_in, const int* in_sizes, int n_in,
                              void* d_out, int out_size) {
    const float* x = nullptr;
    const float* L = nullptr;
    const float* w = nullptr;
    for (int i = 0; i < n_in; i++) {
        if (in_sizes[i] == NVTX * NCH * /*BATCH folded*/ 1 * 10) { /* unused */ }
        if (in_sizes[i] == 8 * NVTX * 3)          x = (const float*)d_in[i];
        else if (in_sizes[i] == NVTX * NVTX)      L = (const float*)d_in[i];
        else if (in_sizes[i] == 1)                w = (const float*)d_in[i];
    }
    float* out = (float*)d_out;

    k_buildx<<<(NVTX * NCH + 255) / 256, 256>>>(x);
    dim3 grid(NRB, 2);
    k_main<<<grid, 256>>>(L);
    k_final<<<8, 256>>>(w, out);
}

// round 2
// speedup vs baseline: 1.2364x; 1.2364x over previous
#include <cuda_runtime.h>
#include <cuda_bf16.h>
#include <cstdint>

// LaplacianLoss: out[b] = ||w * (L @ x[b])||_F * NV
//   L: [NV, NV] f32 (400 MB, streamed once; mesh Laplacian -> ~13 nz/row)
//   x: [8, NV, 3] f32  -> repacked to X[c][j], c = 3*b + k (24 channels)
//   out: 8 f32
//
// v2: warp-uniform zero-skip of the FMA block (L is sparse-in-value, dense in
// storage) turns the GEMM into a pure 400MB DRAM stream with rare FMA bursts.
// Depth-4 register prefetch of L hides DRAM latency. Deterministic (no atomics).

#define NVTX     10000
#define NCH      24            // 8 batches * 3 dims
#define JHALF    5000          // j range per grid.y slice
#define JT       256           // j tile staged in smem
#define RPW      6             // rows per warp (accumulator tile)
#define WARPS    8
#define ROWS_CTA (WARPS * RPW) // 48
#define NRB      ((NVTX + ROWS_CTA - 1) / ROWS_CTA) // 209 row blocks
#define PD       4             // prefetch depth (32-j steps)

typedef unsigned long long ull;

// X repacked as [6][NV] float4: quad q holds channels 4q..4q+3 for vertex j.
__device__ float4 g_X4[6 * NVTX];
// Partial lx: [jhalf][row][12] f32x2 pairs (pair p = channels 2p, 2p+1).
__device__ ull g_part[2 * NVTX * 12];
// Per-(batch, slice) partial sum of squares.
__device__ float g_red[64];

#define FFMA2(d, a, b) asm("fma.rn.f32x2 %0, %1, %2, %0;" : "+l"(d) : "l"(a), "l"(b))
#define FADD2(d, a, b) asm("add.rn.f32x2 %0, %1, %2;" : "=l"(d) : "l"(a), "l"(b))
#define PACK2(d, f)    asm("mov.b64 %0, {%1, %1};"     : "=l"(d) : "f"(f))

// ---------------------------------------------------------------------------
// Kernel 0: repack x[8][NV][3] -> g_X4[c/4][j].{c%4}
// ---------------------------------------------------------------------------
__global__ void k_buildx(const float* __restrict__ x) {
    int idx = blockIdx.x * blockDim.x + threadIdx.x;   // over NV*24
    if (idx >= NVTX * NCH) return;
    int j = idx / NCH;
    int c = idx - j * NCH;
    int b = c / 3;
    int k = c - 3 * b;
    float v = x[(b * NVTX + j) * 3 + k];
    reinterpret_cast<float*>(g_X4)[(c >> 2) * (NVTX * 4) + j * 4 + (c & 3)] = v;
}

// ---------------------------------------------------------------------------
// Kernel 1: main streaming GEMM. grid = (NRB, 2), block = 256.
// ---------------------------------------------------------------------------
__global__ void __launch_bounds__(256) k_main(const float* __restrict__ L) {
    __shared__ float4 Xs[6][JT];

    const int tid  = threadIdx.x;
    const int lane = tid & 31;
    const int warp = tid >> 5;
    const int jh   = blockIdx.y;
    const int row0 = blockIdx.x * ROWS_CTA + warp * RPW;
    const int jbeg = jh * JHALF;

    // accumulators: 6 rows x 12 channel-pairs (f32x2)
    ull acc[RPW][12];
#pragma unroll
    for (int r = 0; r < RPW; r++)
#pragma unroll
        for (int p = 0; p < 12; p++) acc[r][p] = 0ULL;

    // per-row L base pointers (row-clamped; OOB rows guarded at store time)
    const float* Lp[RPW];
#pragma unroll
    for (int r = 0; r < RPW; r++) {
        int rr = row0 + r;
        if (rr >= NVTX) rr = NVTX - 1;
        Lp[r] = L + (size_t)rr * NVTX + jbeg + lane;
    }

    // depth-PD software prefetch of L (steps of 32 j); first PD*32 j in-range
    float Lpre[PD][RPW];
#pragma unroll
    for (int q = 0; q < PD; q++) {
#pragma unroll
        for (int r = 0; r < RPW; r++)
            Lpre[q][r] = __ldcs(Lp[r] + q * 32);
    }

    const int ntiles = (JHALF + JT - 1) / JT;      // 20
    int gs = 0;                                    // global 32-j step index

    for (int t = 0; t < ntiles; t++) {
        // stage X tile (zero-padded past JHALF)
        {
            int jl = t * JT + tid;
            int jg = jbeg + jl;
            float4 z = make_float4(0.f, 0.f, 0.f, 0.f);
            bool ok = (jl < JHALF);
#pragma unroll
            for (int p4 = 0; p4 < 6; p4++)
                Xs[p4][tid] = ok ? __ldg(&g_X4[p4 * NVTX + jg]) : z;
        }
        __syncthreads();

#pragma unroll
        for (int s = 0; s < JT / 32; s++) {
            const int buf = gs & (PD - 1);

            // grab current values before the slot is overwritten
            float cur[RPW];
#pragma unroll
            for (int r = 0; r < RPW; r++) cur[r] = Lpre[buf][r];

            // prefetch step gs+PD (zeroed when OOB)
            {
                int jq  = gs + PD;
                bool ok = (jq * 32 + lane < JHALF);
                int off = ok ? jq * 32 : 0;
#pragma unroll
                for (int r = 0; r < RPW; r++) {
                    float v = __ldcs(Lp[r] + off);
                    Lpre[buf][r] = ok ? v : 0.f;
                }
            }

            // warp-uniform zero test: skip the FMA block if all 192 values are 0
            unsigned u = 0;
#pragma unroll
            for (int r = 0; r < RPW; r++) u |= __float_as_uint(cur[r]);

            if (__ballot_sync(0xffffffffu, u) != 0) {
                ull a[RPW];
#pragma unroll
                for (int r = 0; r < RPW; r++) PACK2(a[r], cur[r]);

                const int xi = s * 32 + lane;
#pragma unroll
                for (int p4 = 0; p4 < 6; p4++) {
                    ulonglong2 xv = *reinterpret_cast<const ulonglong2*>(&Xs[p4][xi]);
#pragma unroll
                    for (int r = 0; r < RPW; r++) {
                        FFMA2(acc[r][2 * p4 + 0], a[r], xv.x);
                        FFMA2(acc[r][2 * p4 + 1], a[r], xv.y);
                    }
                }
            }
            gs++;
        }
        __syncthreads();
    }

    // lane-reduce each (row, pair) across the warp (butterfly, f32x2 adds)
#pragma unroll
    for (int r = 0; r < RPW; r++) {
#pragma unroll
        for (int p = 0; p < 12; p++) {
            ull v = acc[r][p];
#pragma unroll
            for (int m = 16; m >= 1; m >>= 1) {
                ull o = __shfl_xor_sync(0xffffffffu, v, m);
                ull s;
                FADD2(s, v, o);
                v = s;
            }
            acc[r][p] = v;
        }
    }

    if (lane == 0) {
#pragma unroll
        for (int r = 0; r < RPW; r++) {
            int row = row0 + r;
            if (row < NVTX) {
#pragma unroll
                for (int p = 0; p < 12; p++)
                    g_part[((size_t)jh * NVTX + row) * 12 + p] = acc[r][p];
            }
        }
    }
}

// ---------------------------------------------------------------------------
// Kernel 2: partial sum-of-squares. grid = 64 (8 batches x 8 row slices).
// ---------------------------------------------------------------------------
__global__ void k_partial(void) {
    const int b  = blockIdx.x >> 3;
    const int sl = blockIdx.x & 7;
    const int tid = threadIdx.x;
    __shared__ float red[256];

    const float* P = reinterpret_cast<const float*>(g_part); // [jh][row][24]
    const int i0 = sl * (NVTX / 8);
    const int i1 = i0 + (NVTX / 8);

    float s = 0.f;
    for (int idx = i0 * 3 + tid; idx < i1 * 3; idx += 256) {
        int i = idx / 3;
        int k = idx - 3 * i;
        int c = 3 * b + k;
        float v = P[(size_t)i * 24 + c] + P[((size_t)NVTX + i) * 24 + c];
        s += v * v;
    }
    red[tid] = s;
    __syncthreads();
    for (int off = 128; off > 0; off >>= 1) {
        if (tid < off) red[tid] += red[tid + off];
        __syncthreads();
    }
    if (tid == 0) g_red[blockIdx.x] = red[0];
}

// ---------------------------------------------------------------------------
// Kernel 3: finalize. 1 block, 64 threads.
// ---------------------------------------------------------------------------
__global__ void k_final(const float* __restrict__ w, float* __restrict__ out) {
    __shared__ float sh[64];
    int t = threadIdx.x;
    sh[t] = g_red[t];
    __syncthreads();
    if (t < 8) {
        float s = 0.f;
#pragma unroll
        for (int j = 0; j < 8; j++) s += sh[t * 8 + j];
        out[t] = w[0] * (float)NVTX * sqrtf(s);
    }
}

// ---------------------------------------------------------------------------
extern "C" void kernel_launch(void* const* d_in, const int* in_sizes, int n_in,
                              void* d_out, int out_size) {
    const float* x = nullptr;
    const float* L = nullptr;
    const float* w = nullptr;
    for (int i = 0; i < n_in; i++) {
        if (in_sizes[i] == 8 * NVTX * 3)          x = (const float*)d_in[i];
        else if (in_sizes[i] == NVTX * NVTX)      L = (const float*)d_in[i];
        else if (in_sizes[i] == 1)                w = (const float*)d_in[i];
    }
    float* out = (float*)d_out;

    k_buildx<<<(NVTX * NCH + 255) / 256, 256>>>(x);
    dim3 grid(NRB, 2);
    k_main<<<grid, 256>>>(L);
    k_partial<<<64, 256>>>();
    k_final<<<1, 64>>>(w, out);
}